// round 3
// baseline (speedup 1.0000x reference)
#include <cuda_runtime.h>

#define BATCH 4
#define SEQ 2048
#define DMODEL 2048
#define NH 16
#define NKV 4
#define HD 128
#define MROWS (BATCH * SEQ)   // 8192

// ---------------- scratch (device globals: allocation-free) ----------------
__device__ float g_q[(size_t)MROWS * NH * HD];    // [B*S, 16*128]  (= [B,S,H,D])
__device__ float g_k[(size_t)MROWS * NKV * HD];   // [B*S, 4*128]
__device__ float g_v[(size_t)MROWS * NKV * HD];
__device__ float g_o[(size_t)MROWS * NH * HD];    // attention output, pre-Wo

// ---------------- generic fp32 GEMM: C[M,N] = A[M,K] @ B[K,N] --------------
// row-major everywhere; M,N % 64 == 0, K % 16 == 0. 256 threads, 4x4 microtile.
__global__ __launch_bounds__(256)
void gemm64(const float* __restrict__ A, const float* __restrict__ B,
            float* __restrict__ C, int N, int K) {
    __shared__ float As[16][64];   // transposed: As[k][m]
    __shared__ float Bs[16][64];   // Bs[k][n]
    const int tid = threadIdx.x;
    const int tx = tid & 15, ty = tid >> 4;
    const int m0 = blockIdx.y * 64, n0 = blockIdx.x * 64;
    const int ar = tid >> 2, ac = (tid & 3) << 2;     // A: 64 rows x 16 k
    const int br = tid >> 4, bc = (tid & 15) << 2;    // B: 16 k x 64 n

    float acc[4][4] = {};

    for (int k0 = 0; k0 < K; k0 += 16) {
        float4 av = *(const float4*)(A + (size_t)(m0 + ar) * K + (k0 + ac));
        float4 bv = *(const float4*)(B + (size_t)(k0 + br) * N + (n0 + bc));
        __syncthreads();
        As[ac + 0][ar] = av.x; As[ac + 1][ar] = av.y;
        As[ac + 2][ar] = av.z; As[ac + 3][ar] = av.w;
        Bs[br][bc + 0] = bv.x; Bs[br][bc + 1] = bv.y;
        Bs[br][bc + 2] = bv.z; Bs[br][bc + 3] = bv.w;
        __syncthreads();
        #pragma unroll
        for (int kk = 0; kk < 16; kk++) {
            float4 a = *(const float4*)&As[kk][ty * 4];   // 4 rows, vectorized
            float b0 = Bs[kk][tx +  0];                   // strided cols: conflict-free
            float b1 = Bs[kk][tx + 16];
            float b2 = Bs[kk][tx + 32];
            float b3 = Bs[kk][tx + 48];
            acc[0][0] += a.x * b0; acc[0][1] += a.x * b1; acc[0][2] += a.x * b2; acc[0][3] += a.x * b3;
            acc[1][0] += a.y * b0; acc[1][1] += a.y * b1; acc[1][2] += a.y * b2; acc[1][3] += a.y * b3;
            acc[2][0] += a.z * b0; acc[2][1] += a.z * b1; acc[2][2] += a.z * b2; acc[2][3] += a.z * b3;
            acc[3][0] += a.w * b0; acc[3][1] += a.w * b1; acc[3][2] += a.w * b2; acc[3][3] += a.w * b3;
        }
    }
    #pragma unroll
    for (int i = 0; i < 4; i++)
        #pragma unroll
        for (int j = 0; j < 4; j++)
            C[(size_t)(m0 + ty * 4 + i) * N + n0 + tx + 16 * j] = acc[i][j];
}

// ---------------- RoPE (interleaved pairs, matches reference) --------------
__global__ void rope_kernel(float* __restrict__ buf, const float* __restrict__ fc,
                            const float* __restrict__ fs, int heads, int total) {
    int idx = blockIdx.x * blockDim.x + threadIdx.x;
    if (idx >= total) return;
    int i   = idx & (HD / 2 - 1);          // 0..63
    int rh  = idx >> 6;
    int h   = rh % heads;
    int row = rh / heads;                  // b*S + s
    int s   = row & (SEQ - 1);
    float c  = fc[s * (HD / 2) + i];
    float sn = fs[s * (HD / 2) + i];
    float* p = buf + (size_t)row * heads * HD + h * HD + 2 * i;
    float xr = p[0], xi = p[1];
    p[0] = xr * c - xi * sn;
    p[1] = xr * sn + xi * c;
}

// ---------------- flash attention, fp32, causal, GQA -----------------------
// grid: (S/64, NH, B). 256 threads = (tx 0..15, ty 0..15).
// thread owns score rows ty*4+i, score cols tx+16*j, out cols tx+16*c.
#define SMEM_FLOATS 24832           // 99328 bytes
__global__ __launch_bounds__(256, 2)
void attn_kernel(const float* __restrict__ q, const float* __restrict__ k,
                 const float* __restrict__ v, float* __restrict__ o) {
    extern __shared__ float sm[];
    float* sq = sm;                 // 64 x 128           (8192 f)
    float* sk = sm + 8192;          // 64 x 132 (padded)  (8448 f)
    float* sp = sm + 8192;          // 64 x 64  — ALIASES sk after S is computed
    float* sv = sm + 16640;         // 64 x 128           (8192 f)

    const int tid = threadIdx.x;
    const int tx = tid & 15, ty = tid >> 4;
    const int qt = blockIdx.x, h = blockIdx.y, b = blockIdx.z;
    const int kv = h >> 2;          // n_rep = 4
    const size_t rowbase = (size_t)b * SEQ;

    // load Q tile [64 x 128]
    #pragma unroll
    for (int u = 0; u < 8; u++) {
        int f = tid + 256 * u;
        int r = f >> 5, c4 = f & 31;
        *(float4*)(sq + r * 128 + c4 * 4) =
            *(const float4*)(q + (rowbase + qt * 64 + r) * (NH * HD) + h * HD + c4 * 4);
    }

    float acc[4][8] = {};
    float mrun[4] = {-1e30f, -1e30f, -1e30f, -1e30f};
    float lrun[4] = {};
    const float SCALE = 0.08838834764831845f;   // 1/sqrt(128)

    for (int kt = 0; kt <= qt; kt++) {
        __syncthreads();   // prev PV (reads sp/sv) complete
        #pragma unroll
        for (int u = 0; u < 8; u++) {
            int f = tid + 256 * u;
            int r = f >> 5, c4 = f & 31;
            size_t src = (rowbase + kt * 64 + r) * (NKV * HD) + kv * HD + c4 * 4;
            *(float4*)(sk + r * 132 + c4 * 4) = *(const float4*)(k + src);
            *(float4*)(sv + r * 128 + c4 * 4) = *(const float4*)(v + src);
        }
        __syncthreads();

        // S = Q K^T (4x4 per thread), vectorized over k-dim
        float s[4][4] = {};
        #pragma unroll 4
        for (int kk = 0; kk < 128; kk += 4) {
            float4 a[4], bb[4];
            #pragma unroll
            for (int i = 0; i < 4; i++)
                a[i] = *(const float4*)(sq + (ty * 4 + i) * 128 + kk);
            #pragma unroll
            for (int j = 0; j < 4; j++)
                bb[j] = *(const float4*)(sk + (tx + 16 * j) * 132 + kk);
            #pragma unroll
            for (int i = 0; i < 4; i++)
                #pragma unroll
                for (int j = 0; j < 4; j++)
                    s[i][j] += a[i].x * bb[j].x + a[i].y * bb[j].y +
                               a[i].z * bb[j].z + a[i].w * bb[j].w;
        }

        const bool diag = (kt == qt);
        #pragma unroll
        for (int i = 0; i < 4; i++)
            #pragma unroll
            for (int j = 0; j < 4; j++) {
                float val = s[i][j] * SCALE;
                if (diag && (tx + 16 * j) > (ty * 4 + i)) val = -1e30f;
                s[i][j] = val;
            }

        // online softmax: 16-lane row reductions (tx dimension)
        #pragma unroll
        for (int i = 0; i < 4; i++) {
            float rm = fmaxf(fmaxf(s[i][0], s[i][1]), fmaxf(s[i][2], s[i][3]));
            #pragma unroll
            for (int off = 8; off; off >>= 1)
                rm = fmaxf(rm, __shfl_xor_sync(0xffffffffu, rm, off));
            float mnew = fmaxf(mrun[i], rm);
            float corr = __expf(mrun[i] - mnew);
            mrun[i] = mnew;
            float rs = 0.f;
            #pragma unroll
            for (int j = 0; j < 4; j++) {
                float pv = __expf(s[i][j] - mnew);
                s[i][j] = pv;
                rs += pv;
            }
            #pragma unroll
            for (int off = 8; off; off >>= 1)
                rs += __shfl_xor_sync(0xffffffffu, rs, off);
            lrun[i] = lrun[i] * corr + rs;
            #pragma unroll
            for (int c = 0; c < 8; c++) acc[i][c] *= corr;
        }

        __syncthreads();   // all threads done reading sk -> safe to alias with sp
        #pragma unroll
        for (int i = 0; i < 4; i++)
            #pragma unroll
            for (int j = 0; j < 4; j++)
                sp[(ty * 4 + i) * 64 + tx + 16 * j] = s[i][j];
        __syncthreads();

        // acc += P @ V
        #pragma unroll 2
        for (int jj = 0; jj < 64; jj++) {
            float vv[8];
            #pragma unroll
            for (int c = 0; c < 8; c++) vv[c] = sv[jj * 128 + tx + 16 * c];
            #pragma unroll
            for (int i = 0; i < 4; i++) {
                float pv = sp[(ty * 4 + i) * 64 + jj];
                #pragma unroll
                for (int c = 0; c < 8; c++) acc[i][c] += pv * vv[c];
            }
        }
    }

    #pragma unroll
    for (int i = 0; i < 4; i++) {
        float inv = 1.f / lrun[i];
        #pragma unroll
        for (int c = 0; c < 8; c++)
            o[(rowbase + qt * 64 + ty * 4 + i) * (NH * HD) + h * HD + tx + 16 * c] =
                acc[i][c] * inv;
    }
}

// ---------------- launch ----------------------------------------------------
extern "C" void kernel_launch(void* const* d_in, const int* in_sizes, int n_in,
                              void* d_out, int out_size) {
    const float* x  = (const float*)d_in[0];
    const float* fc = (const float*)d_in[1];
    const float* fs = (const float*)d_in[2];
    const float* wq = (const float*)d_in[3];
    const float* wk = (const float*)d_in[4];
    const float* wv = (const float*)d_in[5];
    const float* wo = (const float*)d_in[6];
    float* out = (float*)d_out;

    float *q, *k, *v, *o;
    cudaGetSymbolAddress((void**)&q, g_q);
    cudaGetSymbolAddress((void**)&k, g_k);
    cudaGetSymbolAddress((void**)&v, g_v);
    cudaGetSymbolAddress((void**)&o, g_o);
    cudaFuncSetAttribute(attn_kernel, cudaFuncAttributeMaxDynamicSharedMemorySize,
                         SMEM_FLOATS * 4);

    // projections
    gemm64<<<dim3((NH  * HD) / 64, MROWS / 64), 256>>>(x, wq, q, NH  * HD, DMODEL);
    gemm64<<<dim3((NKV * HD) / 64, MROWS / 64), 256>>>(x, wk, k, NKV * HD, DMODEL);
    gemm64<<<dim3((NKV * HD) / 64, MROWS / 64), 256>>>(x, wv, v, NKV * HD, DMODEL);

    // rope
    {
        int tot = MROWS * NH * (HD / 2);
        rope_kernel<<<(tot + 255) / 256, 256>>>(q, fc, fs, NH, tot);
    }
    {
        int tot = MROWS * NKV * (HD / 2);
        rope_kernel<<<(tot + 255) / 256, 256>>>(k, fc, fs, NKV, tot);
    }

    // attention
    attn_kernel<<<dim3(SEQ / 64, NH, BATCH), 256, SMEM_FLOATS * 4>>>(q, k, v, o);

    // output projection
    gemm64<<<dim3(DMODEL / 64, MROWS / 64), 256>>>(o, wo, out, DMODEL, DMODEL);
}

// round 4
// speedup vs baseline: 2.0556x; 2.0556x over previous
#include <cuda_runtime.h>
#include <cstdint>

#define BATCH 4
#define SEQ 2048
#define DMODEL 2048
#define NH 16
#define NKV 4
#define HD 128
#define MROWS (BATCH * SEQ)   // 8192

// ---------------- scratch (device globals: allocation-free) ----------------
__device__ float g_q[(size_t)MROWS * NH * HD];
__device__ float g_k[(size_t)MROWS * NKV * HD];
__device__ float g_v[(size_t)MROWS * NKV * HD];
__device__ float g_o[(size_t)MROWS * NH * HD];

// ---------------- tf32 helpers ---------------------------------------------
__device__ __forceinline__ uint32_t f2tf(float x) {
    uint32_t r;
    asm("cvt.rna.tf32.f32 %0, %1;" : "=r"(r) : "f"(x));
    return r;
}

__device__ __forceinline__ void mma8(float c[4], const uint32_t a[4], const uint32_t b[2]) {
    asm volatile(
        "mma.sync.aligned.m16n8k8.row.col.f32.tf32.tf32.f32 "
        "{%0,%1,%2,%3}, {%4,%5,%6,%7}, {%8,%9}, {%0,%1,%2,%3};"
        : "+f"(c[0]), "+f"(c[1]), "+f"(c[2]), "+f"(c[3])
        : "r"(a[0]), "r"(a[1]), "r"(a[2]), "r"(a[3]), "r"(b[0]), "r"(b[1]));
}

// ---------------- tf32 tensor-core GEMM: C[M,N] = A[M,K] @ B[K,N] ----------
// row-major; M % 128 == 0, N % 128 == 0, K % 32 == 0.
// 256 threads = 8 warps; CTA tile 128x128, warp tile 32x64, k-tile 32.
#define AS_STRIDE 36    // (4g+c) mod 32 unique  -> conflict-free A frags
#define BS_STRIDE 136   // (8c+g) mod 32 unique  -> conflict-free B frags
__global__ __launch_bounds__(256)
void gemm_tf32(const float* __restrict__ A, const float* __restrict__ B,
               float* __restrict__ C, int N, int K) {
    __shared__ uint32_t As[128 * AS_STRIDE];   // [m][k]
    __shared__ uint32_t Bs[32 * BS_STRIDE];    // [k][n]

    const int tid  = threadIdx.x;
    const int lane = tid & 31, w = tid >> 5;
    const int g = lane >> 2, c = lane & 3;        // groupID / thread-in-group
    const int wm = (w & 3) * 32;                  // warp row offset in CTA tile
    const int wn = (w >> 2) * 64;                 // warp col offset
    const int m0 = blockIdx.y * 128, n0 = blockIdx.x * 128;

    // staging coords
    const int arow = tid >> 3, acol = (tid & 7) * 4;    // A: 32 rows/pass, 4 passes
    const int brow = tid >> 5, bcol = (tid & 31) * 4;   // B: 8 rows/pass, 4 passes

    float acc[2][8][4] = {};

    for (int k0 = 0; k0 < K; k0 += 32) {
        float4 av[4], bv[4];
        #pragma unroll
        for (int i = 0; i < 4; i++)
            av[i] = *(const float4*)(A + (size_t)(m0 + arow + 32 * i) * K + k0 + acol);
        #pragma unroll
        for (int i = 0; i < 4; i++)
            bv[i] = *(const float4*)(B + (size_t)(k0 + brow + 8 * i) * N + n0 + bcol);

        __syncthreads();   // previous k-tile's MMAs done reading smem
        #pragma unroll
        for (int i = 0; i < 4; i++) {
            uint32_t* p = As + (arow + 32 * i) * AS_STRIDE + acol;
            p[0] = f2tf(av[i].x); p[1] = f2tf(av[i].y);
            p[2] = f2tf(av[i].z); p[3] = f2tf(av[i].w);
        }
        #pragma unroll
        for (int i = 0; i < 4; i++) {
            uint32_t* p = Bs + (brow + 8 * i) * BS_STRIDE + bcol;
            p[0] = f2tf(bv[i].x); p[1] = f2tf(bv[i].y);
            p[2] = f2tf(bv[i].z); p[3] = f2tf(bv[i].w);
        }
        __syncthreads();

        #pragma unroll
        for (int kk = 0; kk < 32; kk += 8) {
            uint32_t a[2][4], b[8][2];
            #pragma unroll
            for (int mf = 0; mf < 2; mf++) {
                const uint32_t* ap = As + (wm + mf * 16 + g) * AS_STRIDE + kk + c;
                a[mf][0] = ap[0];
                a[mf][2] = ap[4];
                a[mf][1] = ap[8 * AS_STRIDE];
                a[mf][3] = ap[8 * AS_STRIDE + 4];
            }
            #pragma unroll
            for (int nf = 0; nf < 8; nf++) {
                const uint32_t* bp = Bs + (kk + c) * BS_STRIDE + wn + nf * 8 + g;
                b[nf][0] = bp[0];
                b[nf][1] = bp[4 * BS_STRIDE];
            }
            #pragma unroll
            for (int mf = 0; mf < 2; mf++)
                #pragma unroll
                for (int nf = 0; nf < 8; nf++)
                    mma8(acc[mf][nf], a[mf], b[nf]);
        }
    }

    // epilogue: c0,c1 at (row g, cols 2c,2c+1); c2,c3 at row g+8
    #pragma unroll
    for (int mf = 0; mf < 2; mf++) {
        const size_t r0 = (size_t)(m0 + wm + mf * 16 + g);
        #pragma unroll
        for (int nf = 0; nf < 8; nf++) {
            const int col = n0 + wn + nf * 8 + 2 * c;
            *(float2*)(C + r0 * N + col)       = make_float2(acc[mf][nf][0], acc[mf][nf][1]);
            *(float2*)(C + (r0 + 8) * N + col) = make_float2(acc[mf][nf][2], acc[mf][nf][3]);
        }
    }
}

// ---------------- RoPE (interleaved pairs, matches reference) --------------
__global__ void rope_kernel(float* __restrict__ buf, const float* __restrict__ fc,
                            const float* __restrict__ fs, int heads, int total) {
    int idx = blockIdx.x * blockDim.x + threadIdx.x;
    if (idx >= total) return;
    int i   = idx & (HD / 2 - 1);
    int rh  = idx >> 6;
    int h   = rh % heads;
    int row = rh / heads;
    int s   = row & (SEQ - 1);
    float c  = fc[s * (HD / 2) + i];
    float sn = fs[s * (HD / 2) + i];
    float* p = buf + (size_t)row * heads * HD + h * HD + 2 * i;
    float xr = p[0], xi = p[1];
    p[0] = xr * c - xi * sn;
    p[1] = xr * sn + xi * c;
}

// ---------------- flash attention, fp32, causal, GQA (unchanged) -----------
#define SMEM_FLOATS 24832           // 99328 bytes
__global__ __launch_bounds__(256, 2)
void attn_kernel(const float* __restrict__ q, const float* __restrict__ k,
                 const float* __restrict__ v, float* __restrict__ o) {
    extern __shared__ float sm[];
    float* sq = sm;                 // 64 x 128
    float* sk = sm + 8192;          // 64 x 132 (padded)
    float* sp = sm + 8192;          // 64 x 64  — aliases sk after S computed
    float* sv = sm + 16640;         // 64 x 128

    const int tid = threadIdx.x;
    const int tx = tid & 15, ty = tid >> 4;
    const int qt = blockIdx.x, h = blockIdx.y, b = blockIdx.z;
    const int kv = h >> 2;
    const size_t rowbase = (size_t)b * SEQ;

    #pragma unroll
    for (int u = 0; u < 8; u++) {
        int f = tid + 256 * u;
        int r = f >> 5, c4 = f & 31;
        *(float4*)(sq + r * 128 + c4 * 4) =
            *(const float4*)(q + (rowbase + qt * 64 + r) * (NH * HD) + h * HD + c4 * 4);
    }

    float acc[4][8] = {};
    float mrun[4] = {-1e30f, -1e30f, -1e30f, -1e30f};
    float lrun[4] = {};
    const float SCALE = 0.08838834764831845f;

    for (int kt = 0; kt <= qt; kt++) {
        __syncthreads();
        #pragma unroll
        for (int u = 0; u < 8; u++) {
            int f = tid + 256 * u;
            int r = f >> 5, c4 = f & 31;
            size_t src = (rowbase + kt * 64 + r) * (NKV * HD) + kv * HD + c4 * 4;
            *(float4*)(sk + r * 132 + c4 * 4) = *(const float4*)(k + src);
            *(float4*)(sv + r * 128 + c4 * 4) = *(const float4*)(v + src);
        }
        __syncthreads();

        float s[4][4] = {};
        #pragma unroll 4
        for (int kk = 0; kk < 128; kk += 4) {
            float4 a[4], bb[4];
            #pragma unroll
            for (int i = 0; i < 4; i++)
                a[i] = *(const float4*)(sq + (ty * 4 + i) * 128 + kk);
            #pragma unroll
            for (int j = 0; j < 4; j++)
                bb[j] = *(const float4*)(sk + (tx + 16 * j) * 132 + kk);
            #pragma unroll
            for (int i = 0; i < 4; i++)
                #pragma unroll
                for (int j = 0; j < 4; j++)
                    s[i][j] += a[i].x * bb[j].x + a[i].y * bb[j].y +
                               a[i].z * bb[j].z + a[i].w * bb[j].w;
        }

        const bool diag = (kt == qt);
        #pragma unroll
        for (int i = 0; i < 4; i++)
            #pragma unroll
            for (int j = 0; j < 4; j++) {
                float val = s[i][j] * SCALE;
                if (diag && (tx + 16 * j) > (ty * 4 + i)) val = -1e30f;
                s[i][j] = val;
            }

        #pragma unroll
        for (int i = 0; i < 4; i++) {
            float rm = fmaxf(fmaxf(s[i][0], s[i][1]), fmaxf(s[i][2], s[i][3]));
            #pragma unroll
            for (int off = 8; off; off >>= 1)
                rm = fmaxf(rm, __shfl_xor_sync(0xffffffffu, rm, off));
            float mnew = fmaxf(mrun[i], rm);
            float corr = __expf(mrun[i] - mnew);
            mrun[i] = mnew;
            float rs = 0.f;
            #pragma unroll
            for (int j = 0; j < 4; j++) {
                float pv = __expf(s[i][j] - mnew);
                s[i][j] = pv;
                rs += pv;
            }
            #pragma unroll
            for (int off = 8; off; off >>= 1)
                rs += __shfl_xor_sync(0xffffffffu, rs, off);
            lrun[i] = lrun[i] * corr + rs;
            #pragma unroll
            for (int c = 0; c < 8; c++) acc[i][c] *= corr;
        }

        __syncthreads();
        #pragma unroll
        for (int i = 0; i < 4; i++)
            #pragma unroll
            for (int j = 0; j < 4; j++)
                sp[(ty * 4 + i) * 64 + tx + 16 * j] = s[i][j];
        __syncthreads();

        #pragma unroll 2
        for (int jj = 0; jj < 64; jj++) {
            float vv[8];
            #pragma unroll
            for (int c = 0; c < 8; c++) vv[c] = sv[jj * 128 + tx + 16 * c];
            #pragma unroll
            for (int i = 0; i < 4; i++) {
                float pv = sp[(ty * 4 + i) * 64 + jj];
                #pragma unroll
                for (int c = 0; c < 8; c++) acc[i][c] += pv * vv[c];
            }
        }
    }

    #pragma unroll
    for (int i = 0; i < 4; i++) {
        float inv = 1.f / lrun[i];
        #pragma unroll
        for (int c = 0; c < 8; c++)
            o[(rowbase + qt * 64 + ty * 4 + i) * (NH * HD) + h * HD + tx + 16 * c] =
                acc[i][c] * inv;
    }
}

// ---------------- launch ----------------------------------------------------
extern "C" void kernel_launch(void* const* d_in, const int* in_sizes, int n_in,
                              void* d_out, int out_size) {
    const float* x  = (const float*)d_in[0];
    const float* fc = (const float*)d_in[1];
    const float* fs = (const float*)d_in[2];
    const float* wq = (const float*)d_in[3];
    const float* wk = (const float*)d_in[4];
    const float* wv = (const float*)d_in[5];
    const float* wo = (const float*)d_in[6];
    float* out = (float*)d_out;

    float *q, *k, *v, *o;
    cudaGetSymbolAddress((void**)&q, g_q);
    cudaGetSymbolAddress((void**)&k, g_k);
    cudaGetSymbolAddress((void**)&v, g_v);
    cudaGetSymbolAddress((void**)&o, g_o);
    cudaFuncSetAttribute(attn_kernel, cudaFuncAttributeMaxDynamicSharedMemorySize,
                         SMEM_FLOATS * 4);

    // projections (tf32 tensor cores)
    gemm_tf32<<<dim3((NH  * HD) / 128, MROWS / 128), 256>>>(x, wq, q, NH  * HD, DMODEL);
    gemm_tf32<<<dim3((NKV * HD) / 128, MROWS / 128), 256>>>(x, wk, k, NKV * HD, DMODEL);
    gemm_tf32<<<dim3((NKV * HD) / 128, MROWS / 128), 256>>>(x, wv, v, NKV * HD, DMODEL);

    // rope
    {
        int tot = MROWS * NH * (HD / 2);
        rope_kernel<<<(tot + 255) / 256, 256>>>(q, fc, fs, NH, tot);
    }
    {
        int tot = MROWS * NKV * (HD / 2);
        rope_kernel<<<(tot + 255) / 256, 256>>>(k, fc, fs, NKV, tot);
    }

    // attention (fp32 SIMT, unchanged this round)
    attn_kernel<<<dim3(SEQ / 64, NH, BATCH), 256, SMEM_FLOATS * 4>>>(q, k, v, o);

    // output projection
    gemm_tf32<<<dim3(DMODEL / 128, MROWS / 128), 256>>>(o, wo, out, DMODEL, DMODEL);
}

// round 5
// speedup vs baseline: 3.6070x; 1.7547x over previous
#include <cuda_runtime.h>
#include <cstdint>

#define BATCH 4
#define SEQ 2048
#define DMODEL 2048
#define NH 16
#define NKV 4
#define HD 128
#define MROWS (BATCH * SEQ)   // 8192

// ---------------- scratch (device globals: allocation-free) ----------------
__device__ float g_q[(size_t)MROWS * NH * HD];
__device__ float g_k[(size_t)MROWS * NKV * HD];
__device__ float g_v[(size_t)MROWS * NKV * HD];
__device__ float g_o[(size_t)MROWS * NH * HD];

// ---------------- tf32 helpers ---------------------------------------------
__device__ __forceinline__ uint32_t f2tf(float x) {
    uint32_t r;
    asm("cvt.rna.tf32.f32 %0, %1;" : "=r"(r) : "f"(x));
    return r;
}

__device__ __forceinline__ void mma8(float c[4], const uint32_t a[4], const uint32_t b[2]) {
    asm volatile(
        "mma.sync.aligned.m16n8k8.row.col.f32.tf32.tf32.f32 "
        "{%0,%1,%2,%3}, {%4,%5,%6,%7}, {%8,%9}, {%0,%1,%2,%3};"
        : "+f"(c[0]), "+f"(c[1]), "+f"(c[2]), "+f"(c[3])
        : "r"(a[0]), "r"(a[1]), "r"(a[2]), "r"(a[3]), "r"(b[0]), "r"(b[1]));
}

// ---------------- tf32 tensor-core GEMM: C[M,N] = A[M,K] @ B[K,N] ----------
#define AS_STRIDE 36
#define BS_STRIDE 136
__global__ __launch_bounds__(256)
void gemm_tf32(const float* __restrict__ A, const float* __restrict__ B,
               float* __restrict__ C, int N, int K) {
    __shared__ uint32_t As[128 * AS_STRIDE];   // [m][k]
    __shared__ uint32_t Bs[32 * BS_STRIDE];    // [k][n]

    const int tid  = threadIdx.x;
    const int lane = tid & 31, w = tid >> 5;
    const int g = lane >> 2, c = lane & 3;
    const int wm = (w & 3) * 32;
    const int wn = (w >> 2) * 64;
    const int m0 = blockIdx.y * 128, n0 = blockIdx.x * 128;

    const int arow = tid >> 3, acol = (tid & 7) * 4;
    const int brow = tid >> 5, bcol = (tid & 31) * 4;

    float acc[2][8][4] = {};

    for (int k0 = 0; k0 < K; k0 += 32) {
        float4 av[4], bv[4];
        #pragma unroll
        for (int i = 0; i < 4; i++)
            av[i] = *(const float4*)(A + (size_t)(m0 + arow + 32 * i) * K + k0 + acol);
        #pragma unroll
        for (int i = 0; i < 4; i++)
            bv[i] = *(const float4*)(B + (size_t)(k0 + brow + 8 * i) * N + n0 + bcol);

        __syncthreads();
        #pragma unroll
        for (int i = 0; i < 4; i++) {
            uint32_t* p = As + (arow + 32 * i) * AS_STRIDE + acol;
            p[0] = f2tf(av[i].x); p[1] = f2tf(av[i].y);
            p[2] = f2tf(av[i].z); p[3] = f2tf(av[i].w);
        }
        #pragma unroll
        for (int i = 0; i < 4; i++) {
            uint32_t* p = Bs + (brow + 8 * i) * BS_STRIDE + bcol;
            p[0] = f2tf(bv[i].x); p[1] = f2tf(bv[i].y);
            p[2] = f2tf(bv[i].z); p[3] = f2tf(bv[i].w);
        }
        __syncthreads();

        #pragma unroll
        for (int kk = 0; kk < 32; kk += 8) {
            uint32_t a[2][4], b[8][2];
            #pragma unroll
            for (int mf = 0; mf < 2; mf++) {
                const uint32_t* ap = As + (wm + mf * 16 + g) * AS_STRIDE + kk + c;
                a[mf][0] = ap[0];
                a[mf][2] = ap[4];
                a[mf][1] = ap[8 * AS_STRIDE];
                a[mf][3] = ap[8 * AS_STRIDE + 4];
            }
            #pragma unroll
            for (int nf = 0; nf < 8; nf++) {
                const uint32_t* bp = Bs + (kk + c) * BS_STRIDE + wn + nf * 8 + g;
                b[nf][0] = bp[0];
                b[nf][1] = bp[4 * BS_STRIDE];
            }
            #pragma unroll
            for (int mf = 0; mf < 2; mf++)
                #pragma unroll
                for (int nf = 0; nf < 8; nf++)
                    mma8(acc[mf][nf], a[mf], b[nf]);
        }
    }

    #pragma unroll
    for (int mf = 0; mf < 2; mf++) {
        const size_t r0 = (size_t)(m0 + wm + mf * 16 + g);
        #pragma unroll
        for (int nf = 0; nf < 8; nf++) {
            const int col = n0 + wn + nf * 8 + 2 * c;
            *(float2*)(C + r0 * N + col)       = make_float2(acc[mf][nf][0], acc[mf][nf][1]);
            *(float2*)(C + (r0 + 8) * N + col) = make_float2(acc[mf][nf][2], acc[mf][nf][3]);
        }
    }
}

// ---------------- RoPE (interleaved pairs, matches reference) --------------
__global__ void rope_kernel(float* __restrict__ buf, const float* __restrict__ fc,
                            const float* __restrict__ fs, int heads, int total) {
    int idx = blockIdx.x * blockDim.x + threadIdx.x;
    if (idx >= total) return;
    int i   = idx & (HD / 2 - 1);
    int rh  = idx >> 6;
    int h   = rh % heads;
    int row = rh / heads;
    int s   = row & (SEQ - 1);
    float c  = fc[s * (HD / 2) + i];
    float sn = fs[s * (HD / 2) + i];
    float* p = buf + (size_t)row * heads * HD + h * HD + 2 * i;
    float xr = p[0], xi = p[1];
    p[0] = xr * c - xi * sn;
    p[1] = xr * sn + xi * c;
}

// ---------------- flash attention, tf32 mma, causal, GQA -------------------
// CTA: 128 Q rows, 8 warps x 16 rows; K/V tile 64. Grid (SEQ/128, NH, B).
// smem (u32): sq 128x132 | sk 64x132 | sv 64x136 | sp 128x68 (warp-private rows)
#define ATT_SMEM_BYTES 171008
__global__ __launch_bounds__(256, 1)
void attn_mma(const float* __restrict__ q, const float* __restrict__ k,
              const float* __restrict__ v, float* __restrict__ o) {
    extern __shared__ uint32_t smu[];
    uint32_t* sq = smu;             // 128 x 132 = 16896
    uint32_t* sk = smu + 16896;     // 64 x 132  = 8448
    uint32_t* sv = smu + 25344;     // 64 x 136  = 8704
    uint32_t* sp = smu + 34048;     // 128 x 68  = 8704

    const int tid  = threadIdx.x;
    const int lane = tid & 31, w = tid >> 5;
    const int g = lane >> 2, c = lane & 3;
    const int qt = blockIdx.x, h = blockIdx.y, b = blockIdx.z;
    const int kv = h >> 2;
    const size_t rowbase = (size_t)b * SEQ;
    const int qrow0 = qt * 128;
    const int r0g = w * 16 + g;     // this thread's first local row (second: +8)

    // load Q tile [128 x 128], convert to tf32
    #pragma unroll
    for (int u = 0; u < 16; u++) {
        int f = tid + 256 * u;
        int r = f >> 5, c4 = (f & 31) * 4;
        float4 qa = *(const float4*)(q + (rowbase + qrow0 + r) * (NH * HD) + h * HD + c4);
        uint32_t* p = sq + r * 132 + c4;
        p[0] = f2tf(qa.x); p[1] = f2tf(qa.y); p[2] = f2tf(qa.z); p[3] = f2tf(qa.w);
    }

    float out[16][4] = {};
    float m0 = -1e30f, m1 = -1e30f, l0 = 0.f, l1 = 0.f;
    const float SCALE = 0.08838834764831845f;   // 1/sqrt(128)

    const int ktmax = 2 * qt + 1;
    for (int kt = 0; kt <= ktmax; kt++) {
        __syncthreads();   // previous tile's PV reads of sv complete
        #pragma unroll
        for (int u = 0; u < 8; u++) {
            int f = tid + 256 * u;
            int r = f >> 5, c4 = (f & 31) * 4;
            size_t src = (rowbase + kt * 64 + r) * (NKV * HD) + kv * HD + c4;
            float4 ka = *(const float4*)(k + src);
            float4 va = *(const float4*)(v + src);
            uint32_t* pk = sk + r * 132 + c4;
            pk[0] = f2tf(ka.x); pk[1] = f2tf(ka.y); pk[2] = f2tf(ka.z); pk[3] = f2tf(ka.w);
            uint32_t* pv = sv + r * 136 + c4;
            pv[0] = f2tf(va.x); pv[1] = f2tf(va.y); pv[2] = f2tf(va.z); pv[3] = f2tf(va.w);
        }
        __syncthreads();

        // S = Q K^T : warp computes 16 x 64
        float s[8][4] = {};
        #pragma unroll
        for (int kk = 0; kk < 128; kk += 8) {
            uint32_t a[4];
            const uint32_t* ap = sq + r0g * 132 + kk + c;
            a[0] = ap[0]; a[1] = ap[8 * 132]; a[2] = ap[4]; a[3] = ap[8 * 132 + 4];
            #pragma unroll
            for (int nf = 0; nf < 8; nf++) {
                uint32_t bfr[2];
                const uint32_t* bp = sk + (nf * 8 + g) * 132 + kk + c;
                bfr[0] = bp[0]; bfr[1] = bp[4];
                mma8(s[nf], a, bfr);
            }
        }

        // scale + causal mask
        const bool needmask = (kt >= 2 * qt);
        const int grow0 = qrow0 + r0g, grow1 = grow0 + 8;
        #pragma unroll
        for (int nf = 0; nf < 8; nf++) {
            int col = kt * 64 + nf * 8 + 2 * c;
            s[nf][0] = (needmask && col     > grow0) ? -1e30f : s[nf][0] * SCALE;
            s[nf][1] = (needmask && col + 1 > grow0) ? -1e30f : s[nf][1] * SCALE;
            s[nf][2] = (needmask && col     > grow1) ? -1e30f : s[nf][2] * SCALE;
            s[nf][3] = (needmask && col + 1 > grow1) ? -1e30f : s[nf][3] * SCALE;
        }

        // online softmax (fp32, 4-lane row groups)
        float rm0 = -1e30f, rm1 = -1e30f;
        #pragma unroll
        for (int nf = 0; nf < 8; nf++) {
            rm0 = fmaxf(rm0, fmaxf(s[nf][0], s[nf][1]));
            rm1 = fmaxf(rm1, fmaxf(s[nf][2], s[nf][3]));
        }
        #pragma unroll
        for (int off = 1; off < 4; off <<= 1) {
            rm0 = fmaxf(rm0, __shfl_xor_sync(0xffffffffu, rm0, off));
            rm1 = fmaxf(rm1, __shfl_xor_sync(0xffffffffu, rm1, off));
        }
        float mn0 = fmaxf(m0, rm0), mn1 = fmaxf(m1, rm1);
        float co0 = __expf(m0 - mn0), co1 = __expf(m1 - mn1);
        m0 = mn0; m1 = mn1;

        float rs0 = 0.f, rs1 = 0.f;
        #pragma unroll
        for (int nf = 0; nf < 8; nf++) {
            float p00 = __expf(s[nf][0] - mn0);
            float p01 = __expf(s[nf][1] - mn0);
            float p10 = __expf(s[nf][2] - mn1);
            float p11 = __expf(s[nf][3] - mn1);
            rs0 += p00 + p01;
            rs1 += p10 + p11;
            uint32_t* q0 = sp + r0g * 68 + nf * 8 + 2 * c;
            q0[0] = f2tf(p00); q0[1] = f2tf(p01);
            uint32_t* q1 = sp + (r0g + 8) * 68 + nf * 8 + 2 * c;
            q1[0] = f2tf(p10); q1[1] = f2tf(p11);
        }
        #pragma unroll
        for (int off = 1; off < 4; off <<= 1) {
            rs0 += __shfl_xor_sync(0xffffffffu, rs0, off);
            rs1 += __shfl_xor_sync(0xffffffffu, rs1, off);
        }
        l0 = l0 * co0 + rs0;
        l1 = l1 * co1 + rs1;
        #pragma unroll
        for (int nf = 0; nf < 16; nf++) {
            out[nf][0] *= co0; out[nf][1] *= co0;
            out[nf][2] *= co1; out[nf][3] *= co1;
        }
        __syncwarp();   // sp rows are warp-private; make lane writes visible

        // out += P @ V : warp's 16 rows x 128 hd
        #pragma unroll
        for (int kk = 0; kk < 64; kk += 8) {
            uint32_t a[4];
            const uint32_t* ap = sp + r0g * 68 + kk + c;
            a[0] = ap[0]; a[1] = ap[8 * 68]; a[2] = ap[4]; a[3] = ap[8 * 68 + 4];
            #pragma unroll
            for (int nf = 0; nf < 16; nf++) {
                uint32_t bfr[2];
                const uint32_t* bp = sv + (kk + c) * 136 + nf * 8 + g;
                bfr[0] = bp[0]; bfr[1] = bp[4 * 136];
                mma8(out[nf], a, bfr);
            }
        }
        __syncwarp();   // all lanes done reading sp before next tile overwrites
    }

    // epilogue
    const float i0 = 1.f / l0, i1 = 1.f / l1;
    const size_t gr0 = rowbase + qrow0 + r0g;
    #pragma unroll
    for (int nf = 0; nf < 16; nf++) {
        const int col = h * HD + nf * 8 + 2 * c;
        *(float2*)(o + gr0 * (NH * HD) + col)       = make_float2(out[nf][0] * i0, out[nf][1] * i0);
        *(float2*)(o + (gr0 + 8) * (NH * HD) + col) = make_float2(out[nf][2] * i1, out[nf][3] * i1);
    }
}

// ---------------- launch ----------------------------------------------------
extern "C" void kernel_launch(void* const* d_in, const int* in_sizes, int n_in,
                              void* d_out, int out_size) {
    const float* x  = (const float*)d_in[0];
    const float* fc = (const float*)d_in[1];
    const float* fs = (const float*)d_in[2];
    const float* wq = (const float*)d_in[3];
    const float* wk = (const float*)d_in[4];
    const float* wv = (const float*)d_in[5];
    const float* wo = (const float*)d_in[6];
    float* out = (float*)d_out;

    float *q, *k, *v, *o;
    cudaGetSymbolAddress((void**)&q, g_q);
    cudaGetSymbolAddress((void**)&k, g_k);
    cudaGetSymbolAddress((void**)&v, g_v);
    cudaGetSymbolAddress((void**)&o, g_o);
    cudaFuncSetAttribute(attn_mma, cudaFuncAttributeMaxDynamicSharedMemorySize,
                         ATT_SMEM_BYTES);

    // projections (tf32 tensor cores)
    gemm_tf32<<<dim3((NH  * HD) / 128, MROWS / 128), 256>>>(x, wq, q, NH  * HD, DMODEL);
    gemm_tf32<<<dim3((NKV * HD) / 128, MROWS / 128), 256>>>(x, wk, k, NKV * HD, DMODEL);
    gemm_tf32<<<dim3((NKV * HD) / 128, MROWS / 128), 256>>>(x, wv, v, NKV * HD, DMODEL);

    // rope
    {
        int tot = MROWS * NH * (HD / 2);
        rope_kernel<<<(tot + 255) / 256, 256>>>(q, fc, fs, NH, tot);
    }
    {
        int tot = MROWS * NKV * (HD / 2);
        rope_kernel<<<(tot + 255) / 256, 256>>>(k, fc, fs, NKV, tot);
    }

    // attention (tf32 mma flash attention)
    attn_mma<<<dim3(SEQ / 128, NH, BATCH), 256, ATT_SMEM_BYTES>>>(q, k, v, o);

    // output projection
    gemm_tf32<<<dim3(DMODEL / 128, MROWS / 128), 256>>>(o, wo, out, DMODEL, DMODEL);
}

// round 8
// speedup vs baseline: 4.6418x; 1.2869x over previous
#include <cuda_runtime.h>
#include <cuda_fp16.h>
#include <cstdint>

#define BATCH 4
#define SEQ 2048
#define DMODEL 2048
#define NH 16
#define NKV 4
#define HD 128
#define MROWS (BATCH * SEQ)   // 8192

// ---------------- scratch (device globals: allocation-free) ----------------
__device__ float g_q[(size_t)MROWS * NH * HD];
__device__ float g_k[(size_t)MROWS * NKV * HD];
__device__ float g_v[(size_t)MROWS * NKV * HD];
__device__ float g_o[(size_t)MROWS * NH * HD];

// ---------------- helpers ---------------------------------------------------
__device__ __forceinline__ uint32_t pk(float x, float y) {
    __half2 h = __floats2half2_rn(x, y);
    return *(uint32_t*)&h;
}

__device__ __forceinline__ uint32_t smem_u32(const void* p) {
    uint32_t a;
    asm("{ .reg .u64 t; cvta.to.shared.u64 t, %1; cvt.u32.u64 %0, t; }"
        : "=r"(a) : "l"(p));
    return a;
}

// fp16 mma m16n8k16, fp32 accumulate
__device__ __forceinline__ void mma16(float c[4], const uint32_t a[4], const uint32_t b[2]) {
    asm volatile(
        "mma.sync.aligned.m16n8k16.row.col.f32.f16.f16.f32 "
        "{%0,%1,%2,%3}, {%4,%5,%6,%7}, {%8,%9}, {%0,%1,%2,%3};"
        : "+f"(c[0]), "+f"(c[1]), "+f"(c[2]), "+f"(c[3])
        : "r"(a[0]), "r"(a[1]), "r"(a[2]), "r"(a[3]), "r"(b[0]), "r"(b[1]));
}

// ---------------- fp16 tensor-core GEMM: C[M,N] = A[M,K] @ B[K,N] ----------
// row-major; M % 128 == 0, N % 128 == 0, K % 32 == 0.
// 256 threads = 8 warps; CTA tile 128x128, warp tile 32x64, k-tile 32.
// Smem words are half2 (2 k-values for A rows / 2 k-values for B cols).
#define AS 20     // words/row (16 used): banks (4g+c) conflict-free
#define BS 136    // words/krow (128 used): banks (8c+g) conflict-free
__global__ __launch_bounds__(256)
void gemm_f16(const float* __restrict__ A, const float* __restrict__ B,
              float* __restrict__ C, int N, int K) {
    __shared__ uint32_t As_[128 * AS];   // [m][kword]
    __shared__ uint32_t Bs_[16 * BS];    // [kword][n]

    const int tid  = threadIdx.x;
    const int lane = tid & 31, w = tid >> 5;
    const int g = lane >> 2, c = lane & 3;
    const int wm = (w & 3) * 32;
    const int wn = (w >> 2) * 64;
    const int m0 = blockIdx.y * 128, n0 = blockIdx.x * 128;

    float acc[2][8][4] = {};

    for (int k0 = 0; k0 < K; k0 += 32) {
        // stage A: 128 rows x 32 k. task idx: r = idx>>3, kq = idx&7 (float4)
        float4 av[4];
        #pragma unroll
        for (int u = 0; u < 4; u++) {
            int idx = tid + (u << 8);
            int r = idx >> 3, kq = idx & 7;
            av[u] = *(const float4*)(A + (size_t)(m0 + r) * K + k0 + kq * 4);
        }
        // stage B: 16 kwords x 128 n. task idx: kw = idx>>5, n4 = idx&31
        float4 b0v[2], b1v[2];
        #pragma unroll
        for (int u = 0; u < 2; u++) {
            int idx = tid + (u << 8);
            int kw = idx >> 5, n4 = idx & 31;
            b0v[u] = *(const float4*)(B + (size_t)(k0 + 2 * kw)     * N + n0 + n4 * 4);
            b1v[u] = *(const float4*)(B + (size_t)(k0 + 2 * kw + 1) * N + n0 + n4 * 4);
        }

        __syncthreads();   // previous k-tile mmas done with smem
        #pragma unroll
        for (int u = 0; u < 4; u++) {
            int idx = tid + (u << 8);
            int r = idx >> 3, kq = idx & 7;
            uint32_t* p = As_ + r * AS + kq * 2;
            p[0] = pk(av[u].x, av[u].y);
            p[1] = pk(av[u].z, av[u].w);
        }
        #pragma unroll
        for (int u = 0; u < 2; u++) {
            int idx = tid + (u << 8);
            int kw = idx >> 5, n4 = idx & 31;
            uint32_t* p = Bs_ + kw * BS + n4 * 4;
            p[0] = pk(b0v[u].x, b1v[u].x);
            p[1] = pk(b0v[u].y, b1v[u].y);
            p[2] = pk(b0v[u].z, b1v[u].z);
            p[3] = pk(b0v[u].w, b1v[u].w);
        }
        __syncthreads();

        #pragma unroll
        for (int ks = 0; ks < 2; ks++) {
            uint32_t a[2][4], b[8][2];
            #pragma unroll
            for (int mf = 0; mf < 2; mf++) {
                const uint32_t* ap = As_ + (wm + mf * 16 + g) * AS + ks * 8 + c;
                a[mf][0] = ap[0];
                a[mf][1] = ap[8 * AS];
                a[mf][2] = ap[4];
                a[mf][3] = ap[8 * AS + 4];
            }
            #pragma unroll
            for (int nf = 0; nf < 8; nf++) {
                const uint32_t* bp = Bs_ + (ks * 8 + c) * BS + wn + nf * 8 + g;
                b[nf][0] = bp[0];
                b[nf][1] = bp[4 * BS];
            }
            #pragma unroll
            for (int mf = 0; mf < 2; mf++)
                #pragma unroll
                for (int nf = 0; nf < 8; nf++)
                    mma16(acc[mf][nf], a[mf], b[nf]);
        }
    }

    // epilogue: c0,c1 at (row g, cols 2c,2c+1); c2,c3 at row g+8
    #pragma unroll
    for (int mf = 0; mf < 2; mf++) {
        const size_t r0 = (size_t)(m0 + wm + mf * 16 + g);
        #pragma unroll
        for (int nf = 0; nf < 8; nf++) {
            const int col = n0 + wn + nf * 8 + 2 * c;
            *(float2*)(C + r0 * N + col)       = make_float2(acc[mf][nf][0], acc[mf][nf][1]);
            *(float2*)(C + (r0 + 8) * N + col) = make_float2(acc[mf][nf][2], acc[mf][nf][3]);
        }
    }
}

// ---------------- RoPE (interleaved pairs, matches reference) --------------
__global__ void rope_kernel(float* __restrict__ buf, const float* __restrict__ fc,
                            const float* __restrict__ fs, int heads, int total) {
    int idx = blockIdx.x * blockDim.x + threadIdx.x;
    if (idx >= total) return;
    int i   = idx & (HD / 2 - 1);
    int rh  = idx >> 6;
    int h   = rh % heads;
    int row = rh / heads;
    int s   = row & (SEQ - 1);
    float c  = fc[s * (HD / 2) + i];
    float sn = fs[s * (HD / 2) + i];
    float* p = buf + (size_t)row * heads * HD + h * HD + 2 * i;
    float xr = p[0], xi = p[1];
    p[0] = xr * c - xi * sn;
    p[1] = xr * sn + xi * c;
}

// ---------------- flash attention, fp16 mma, causal, GQA -------------------
// CTA: 128 Q rows, 8 warps x 16 rows; K/V tile 64. Grid (SEQ/128, NH, B).
// smem words(half2): sq 128x68 | sk 64x68 | sv 64x68 (row-major [key][hd],
// PV B-frags via ldmatrix.trans) | sp 128x36 (warp-private rows)
#define ATT_SMEM_BYTES 88064
__global__ __launch_bounds__(256)
void attn_f16(const float* __restrict__ q, const float* __restrict__ k,
              const float* __restrict__ v, float* __restrict__ o) {
    extern __shared__ uint32_t smu[];
    uint32_t* sq = smu;              // 128 x 68 = 8704
    uint32_t* sk = smu + 8704;       // 64 x 68  = 4352
    uint32_t* sv = smu + 13056;      // 64 x 68  = 4352
    uint32_t* sp = smu + 17408;      // 128 x 36 = 4608
    const uint32_t svb = smem_u32(sv);

    const int tid  = threadIdx.x;
    const int lane = tid & 31, w = tid >> 5;
    const int g = lane >> 2, c = lane & 3;
    const int qt = blockIdx.x, h = blockIdx.y, b = blockIdx.z;
    const int kv = h >> 2;
    const size_t rowbase = (size_t)b * SEQ;
    const int qrow0 = qt * 128;
    const int r0g = w * 16 + g;

    // ldmatrix per-lane address offset (row/col within a 16x16 V block)
    const int lm_row = (lane & 7) + ((lane >> 3) & 1) * 8;
    const int lm_colw = (lane >> 4) * 4;

    // load Q tile [128 x 128] -> half2
    #pragma unroll
    for (int u = 0; u < 16; u++) {
        int f = tid + 256 * u;
        int r = f >> 5, c4 = f & 31;
        float4 qa = *(const float4*)(q + (rowbase + qrow0 + r) * (NH * HD) + h * HD + c4 * 4);
        uint32_t* p = sq + r * 68 + c4 * 2;
        p[0] = pk(qa.x, qa.y); p[1] = pk(qa.z, qa.w);
    }

    float out[16][4] = {};
    float m0 = -1e30f, m1 = -1e30f, l0 = 0.f, l1 = 0.f;
    const float SCALE = 0.08838834764831845f;   // 1/sqrt(128)

    const int ktmax = 2 * qt + 1;
    for (int kt = 0; kt <= ktmax; kt++) {
        __syncthreads();   // previous tile's PV reads complete
        #pragma unroll
        for (int u = 0; u < 8; u++) {
            int f = tid + 256 * u;
            int r = f >> 5, c4 = f & 31;
            size_t src = (rowbase + kt * 64 + r) * (NKV * HD) + kv * HD + c4 * 4;
            float4 ka = *(const float4*)(k + src);
            float4 va = *(const float4*)(v + src);
            uint32_t* pkp = sk + r * 68 + c4 * 2;
            pkp[0] = pk(ka.x, ka.y); pkp[1] = pk(ka.z, ka.w);
            uint32_t* pvp = sv + r * 68 + c4 * 2;
            pvp[0] = pk(va.x, va.y); pvp[1] = pk(va.z, va.w);
        }
        __syncthreads();

        // S = Q K^T : warp computes 16 x 64 (k-dim = hd, 8 ksteps of 16)
        float s[8][4] = {};
        #pragma unroll
        for (int ks = 0; ks < 8; ks++) {
            uint32_t a[4];
            const uint32_t* ap = sq + r0g * 68 + ks * 8 + c;
            a[0] = ap[0]; a[1] = ap[8 * 68]; a[2] = ap[4]; a[3] = ap[8 * 68 + 4];
            #pragma unroll
            for (int nf = 0; nf < 8; nf++) {
                uint32_t bfr[2];
                const uint32_t* bp = sk + (nf * 8 + g) * 68 + ks * 8 + c;
                bfr[0] = bp[0]; bfr[1] = bp[4];
                mma16(s[nf], a, bfr);
            }
        }

        // scale + causal mask
        const bool needmask = (kt >= 2 * qt);
        const int grow0 = qrow0 + r0g, grow1 = grow0 + 8;
        #pragma unroll
        for (int nf = 0; nf < 8; nf++) {
            int col = kt * 64 + nf * 8 + 2 * c;
            s[nf][0] = (needmask && col     > grow0) ? -1e30f : s[nf][0] * SCALE;
            s[nf][1] = (needmask && col + 1 > grow0) ? -1e30f : s[nf][1] * SCALE;
            s[nf][2] = (needmask && col     > grow1) ? -1e30f : s[nf][2] * SCALE;
            s[nf][3] = (needmask && col + 1 > grow1) ? -1e30f : s[nf][3] * SCALE;
        }

        // online softmax (fp32, 4-lane row groups)
        float rm0 = -1e30f, rm1 = -1e30f;
        #pragma unroll
        for (int nf = 0; nf < 8; nf++) {
            rm0 = fmaxf(rm0, fmaxf(s[nf][0], s[nf][1]));
            rm1 = fmaxf(rm1, fmaxf(s[nf][2], s[nf][3]));
        }
        #pragma unroll
        for (int off = 1; off < 4; off <<= 1) {
            rm0 = fmaxf(rm0, __shfl_xor_sync(0xffffffffu, rm0, off));
            rm1 = fmaxf(rm1, __shfl_xor_sync(0xffffffffu, rm1, off));
        }
        float mn0 = fmaxf(m0, rm0), mn1 = fmaxf(m1, rm1);
        float co0 = __expf(m0 - mn0), co1 = __expf(m1 - mn1);
        m0 = mn0; m1 = mn1;

        float rs0 = 0.f, rs1 = 0.f;
        #pragma unroll
        for (int nf = 0; nf < 8; nf++) {
            float p00 = __expf(s[nf][0] - mn0);
            float p01 = __expf(s[nf][1] - mn0);
            float p10 = __expf(s[nf][2] - mn1);
            float p11 = __expf(s[nf][3] - mn1);
            rs0 += p00 + p01;
            rs1 += p10 + p11;
            sp[r0g * 36 + nf * 4 + c]       = pk(p00, p01);
            sp[(r0g + 8) * 36 + nf * 4 + c] = pk(p10, p11);
        }
        #pragma unroll
        for (int off = 1; off < 4; off <<= 1) {
            rs0 += __shfl_xor_sync(0xffffffffu, rs0, off);
            rs1 += __shfl_xor_sync(0xffffffffu, rs1, off);
        }
        l0 = l0 * co0 + rs0;
        l1 = l1 * co1 + rs1;
        #pragma unroll
        for (int nf = 0; nf < 16; nf++) {
            out[nf][0] *= co0; out[nf][1] *= co0;
            out[nf][2] *= co1; out[nf][3] *= co1;
        }
        __syncwarp();   // sp rows are warp-private

        // out += P @ V : 4 ksteps of 16 keys; B frags via ldmatrix.trans
        #pragma unroll
        for (int ks = 0; ks < 4; ks++) {
            uint32_t a[4];
            const uint32_t* ap = sp + r0g * 36 + ks * 8 + c;
            a[0] = ap[0]; a[1] = ap[8 * 36]; a[2] = ap[4]; a[3] = ap[8 * 36 + 4];
            const uint32_t rowaddr = svb + ((ks * 16 + lm_row) * 68 + lm_colw) * 4;
            #pragma unroll
            for (int nf2 = 0; nf2 < 8; nf2++) {
                uint32_t d0, d1, d2, d3;
                asm volatile(
                    "ldmatrix.sync.aligned.m8n8.x4.trans.shared.b16 "
                    "{%0,%1,%2,%3}, [%4];"
                    : "=r"(d0), "=r"(d1), "=r"(d2), "=r"(d3)
                    : "r"(rowaddr + (uint32_t)(nf2 * 8 * 4)));
                uint32_t bA[2] = {d0, d1}, bB[2] = {d2, d3};
                mma16(out[2 * nf2],     a, bA);
                mma16(out[2 * nf2 + 1], a, bB);
            }
        }
        __syncwarp();   // lanes done reading sp before next tile overwrites
    }

    // epilogue
    const float i0 = 1.f / l0, i1 = 1.f / l1;
    const size_t gr0 = rowbase + qrow0 + r0g;
    #pragma unroll
    for (int nf = 0; nf < 16; nf++) {
        const int col = h * HD + nf * 8 + 2 * c;
        *(float2*)(o + gr0 * (NH * HD) + col)       = make_float2(out[nf][0] * i0, out[nf][1] * i0);
        *(float2*)(o + (gr0 + 8) * (NH * HD) + col) = make_float2(out[nf][2] * i1, out[nf][3] * i1);
    }
}

// ---------------- launch ----------------------------------------------------
extern "C" void kernel_launch(void* const* d_in, const int* in_sizes, int n_in,
                              void* d_out, int out_size) {
    const float* x  = (const float*)d_in[0];
    const float* fc = (const float*)d_in[1];
    const float* fs = (const float*)d_in[2];
    const float* wq = (const float*)d_in[3];
    const float* wk = (const float*)d_in[4];
    const float* wv = (const float*)d_in[5];
    const float* wo = (const float*)d_in[6];
    float* out = (float*)d_out;

    float *q, *k, *v, *o;
    cudaGetSymbolAddress((void**)&q, g_q);
    cudaGetSymbolAddress((void**)&k, g_k);
    cudaGetSymbolAddress((void**)&v, g_v);
    cudaGetSymbolAddress((void**)&o, g_o);
    cudaFuncSetAttribute(attn_f16, cudaFuncAttributeMaxDynamicSharedMemorySize,
                         ATT_SMEM_BYTES);

    // projections (fp16 tensor cores)
    gemm_f16<<<dim3((NH  * HD) / 128, MROWS / 128), 256>>>(x, wq, q, NH  * HD, DMODEL);
    gemm_f16<<<dim3((NKV * HD) / 128, MROWS / 128), 256>>>(x, wk, k, NKV * HD, DMODEL);
    gemm_f16<<<dim3((NKV * HD) / 128, MROWS / 128), 256>>>(x, wv, v, NKV * HD, DMODEL);

    // rope
    {
        int tot = MROWS * NH * (HD / 2);
        rope_kernel<<<(tot + 255) / 256, 256>>>(q, fc, fs, NH, tot);
    }
    {
        int tot = MROWS * NKV * (HD / 2);
        rope_kernel<<<(tot + 255) / 256, 256>>>(k, fc, fs, NKV, tot);
    }

    // attention (fp16 mma flash attention)
    attn_f16<<<dim3(SEQ / 128, NH, BATCH), 256, ATT_SMEM_BYTES>>>(q, k, v, o);

    // output projection
    gemm_f16<<<dim3(DMODEL / 128, MROWS / 128), 256>>>(o, wo, out, DMODEL, DMODEL);
}

// round 9
// speedup vs baseline: 5.8867x; 1.2682x over previous
#include <cuda_runtime.h>
#include <cuda_fp16.h>
#include <cstdint>

#define BATCH 4
#define SEQ 2048
#define DMODEL 2048
#define NH 16
#define NKV 4
#define HD 128
#define MROWS (BATCH * SEQ)   // 8192

// ---------------- scratch (device globals: allocation-free) ----------------
__device__ float g_q[(size_t)MROWS * NH * HD];
__device__ float g_k[(size_t)MROWS * NKV * HD];
__device__ float g_v[(size_t)MROWS * NKV * HD];
__device__ float g_o[(size_t)MROWS * NH * HD];

// ---------------- helpers ---------------------------------------------------
__device__ __forceinline__ uint32_t pk(float x, float y) {
    __half2 h = __floats2half2_rn(x, y);
    return *(uint32_t*)&h;
}

__device__ __forceinline__ uint32_t smem_u32(const void* p) {
    uint32_t a;
    asm("{ .reg .u64 t; cvta.to.shared.u64 t, %1; cvt.u32.u64 %0, t; }"
        : "=r"(a) : "l"(p));
    return a;
}

// fp16 mma m16n8k16, fp32 accumulate
__device__ __forceinline__ void mma16(float c[4], const uint32_t a[4], const uint32_t b[2]) {
    asm volatile(
        "mma.sync.aligned.m16n8k16.row.col.f32.f16.f16.f32 "
        "{%0,%1,%2,%3}, {%4,%5,%6,%7}, {%8,%9}, {%0,%1,%2,%3};"
        : "+f"(c[0]), "+f"(c[1]), "+f"(c[2]), "+f"(c[3])
        : "r"(a[0]), "r"(a[1]), "r"(a[2]), "r"(a[3]), "r"(b[0]), "r"(b[1]));
}

#define LDSM4(r0, r1, r2, r3, addr)                                            \
    asm volatile("ldmatrix.sync.aligned.m8n8.x4.shared.b16 {%0,%1,%2,%3}, [%4];" \
        : "=r"(r0), "=r"(r1), "=r"(r2), "=r"(r3) : "r"(addr))

// ---------------- fp16 tensor-core GEMM: C[M,N] = A[M,K] @ B[K,N] ----------
// row-major; M % 128 == 0, N % 128 == 0, K % 32 == 0.
// 256 threads = 8 warps; CTA tile 128x128, warp tile 32x64, k-tile 32.
// Double-buffered smem (1 barrier/tile); A frags via ldmatrix.x4.
#define AS 20     // words/row (16 used)
#define BS 136    // words/krow (128 used): banks (8c+g) conflict-free
__global__ __launch_bounds__(256)
void gemm_f16(const float* __restrict__ A, const float* __restrict__ B,
              float* __restrict__ C, int N, int K) {
    __shared__ uint32_t As_[2][128 * AS];   // [m][kword]
    __shared__ uint32_t Bs_[2][16 * BS];    // [kword][n]

    const int tid  = threadIdx.x;
    const int lane = tid & 31, w = tid >> 5;
    const int g = lane >> 2, c = lane & 3;
    const int wm = (w & 3) * 32;
    const int wn = (w >> 2) * 64;
    const int m0 = blockIdx.y * 128, n0 = blockIdx.x * 128;

    // ldmatrix lane addressing (row within 16-block, word col within kstep)
    const int lmrow = (lane & 7) + ((lane >> 3) & 1) * 8;
    const int lmcol = (lane >> 4) * 4;

    const int ar = tid >> 3, akq = tid & 7;     // A staging: 32 rows per pass
    const int bkw = tid >> 5, bn4 = tid & 31;   // B staging: 8 kwords per pass

    float acc[2][8][4] = {};
    float4 av[4], b0v[2], b1v[2];

    // ---- prefetch + stage tile 0 ----
    #pragma unroll
    for (int u = 0; u < 4; u++)
        av[u] = *(const float4*)(A + (size_t)(m0 + ar + 32 * u) * K + akq * 4);
    #pragma unroll
    for (int u = 0; u < 2; u++) {
        int kw = bkw + 8 * u;
        b0v[u] = *(const float4*)(B + (size_t)(2 * kw)     * N + n0 + bn4 * 4);
        b1v[u] = *(const float4*)(B + (size_t)(2 * kw + 1) * N + n0 + bn4 * 4);
    }
    #pragma unroll
    for (int u = 0; u < 4; u++) {
        uint32_t* p = As_[0] + (ar + 32 * u) * AS + akq * 2;
        p[0] = pk(av[u].x, av[u].y); p[1] = pk(av[u].z, av[u].w);
    }
    #pragma unroll
    for (int u = 0; u < 2; u++) {
        uint32_t* p = Bs_[0] + (bkw + 8 * u) * BS + bn4 * 4;
        p[0] = pk(b0v[u].x, b1v[u].x); p[1] = pk(b0v[u].y, b1v[u].y);
        p[2] = pk(b0v[u].z, b1v[u].z); p[3] = pk(b0v[u].w, b1v[u].w);
    }
    __syncthreads();

    const int ntiles = K >> 5;
    for (int i = 0; i < ntiles; i++) {
        const int buf = i & 1;
        const bool more = (i + 1 < ntiles);
        const int k1 = (i + 1) << 5;

        // prefetch next tile into registers (overlaps mma below)
        if (more) {
            #pragma unroll
            for (int u = 0; u < 4; u++)
                av[u] = *(const float4*)(A + (size_t)(m0 + ar + 32 * u) * K + k1 + akq * 4);
            #pragma unroll
            for (int u = 0; u < 2; u++) {
                int kw = bkw + 8 * u;
                b0v[u] = *(const float4*)(B + (size_t)(k1 + 2 * kw)     * N + n0 + bn4 * 4);
                b1v[u] = *(const float4*)(B + (size_t)(k1 + 2 * kw + 1) * N + n0 + bn4 * 4);
            }
        }

        // mma from current buffer
        const uint32_t asb = smem_u32(As_[buf]);
        #pragma unroll
        for (int ks = 0; ks < 2; ks++) {
            uint32_t a[2][4], b[8][2];
            #pragma unroll
            for (int mf = 0; mf < 2; mf++) {
                uint32_t addr = asb + (uint32_t)(((wm + mf * 16 + lmrow) * AS
                                                  + ks * 8 + lmcol) * 4);
                LDSM4(a[mf][0], a[mf][1], a[mf][2], a[mf][3], addr);
            }
            #pragma unroll
            for (int nf = 0; nf < 8; nf++) {
                const uint32_t* bp = Bs_[buf] + (ks * 8 + c) * BS + wn + nf * 8 + g;
                b[nf][0] = bp[0];
                b[nf][1] = bp[4 * BS];
            }
            #pragma unroll
            for (int mf = 0; mf < 2; mf++)
                #pragma unroll
                for (int nf = 0; nf < 8; nf++)
                    mma16(acc[mf][nf], a[mf], b[nf]);
        }

        // stage next tile into other buffer (safe: its last readers finished
        // before the previous barrier)
        if (more) {
            #pragma unroll
            for (int u = 0; u < 4; u++) {
                uint32_t* p = As_[buf ^ 1] + (ar + 32 * u) * AS + akq * 2;
                p[0] = pk(av[u].x, av[u].y); p[1] = pk(av[u].z, av[u].w);
            }
            #pragma unroll
            for (int u = 0; u < 2; u++) {
                uint32_t* p = Bs_[buf ^ 1] + (bkw + 8 * u) * BS + bn4 * 4;
                p[0] = pk(b0v[u].x, b1v[u].x); p[1] = pk(b0v[u].y, b1v[u].y);
                p[2] = pk(b0v[u].z, b1v[u].z); p[3] = pk(b0v[u].w, b1v[u].w);
            }
        }
        __syncthreads();
    }

    // epilogue: c0,c1 at (row g, cols 2c,2c+1); c2,c3 at row g+8
    #pragma unroll
    for (int mf = 0; mf < 2; mf++) {
        const size_t r0 = (size_t)(m0 + wm + mf * 16 + g);
        #pragma unroll
        for (int nf = 0; nf < 8; nf++) {
            const int col = n0 + wn + nf * 8 + 2 * c;
            *(float2*)(C + r0 * N + col)       = make_float2(acc[mf][nf][0], acc[mf][nf][1]);
            *(float2*)(C + (r0 + 8) * N + col) = make_float2(acc[mf][nf][2], acc[mf][nf][3]);
        }
    }
}

// ---------------- RoPE (interleaved pairs, float2-vectorized) --------------
__global__ void rope_kernel(float* __restrict__ buf, const float* __restrict__ fc,
                            const float* __restrict__ fs, int heads, int total) {
    int idx = blockIdx.x * blockDim.x + threadIdx.x;
    if (idx >= total) return;
    int i   = idx & (HD / 2 - 1);
    int rh  = idx >> 6;
    int h   = rh % heads;
    int row = rh / heads;
    int s   = row & (SEQ - 1);
    float c  = fc[s * (HD / 2) + i];
    float sn = fs[s * (HD / 2) + i];
    float2* p = (float2*)(buf + (size_t)row * heads * HD + h * HD) + i;
    float2 xv = *p;
    *p = make_float2(xv.x * c - xv.y * sn, xv.x * sn + xv.y * c);
}

// ---------------- flash attention, fp16 mma, causal, GQA -------------------
// CTA: 128 Q rows, 8 warps x 16 rows; K/V tile 64. Grid (SEQ/128, NH, B).
// smem words(half2): sq 128x68 | sk 64x68 | sv 64x68 | sp 128x36
#define ATT_SMEM_BYTES 88064
__global__ __launch_bounds__(256)
void attn_f16(const float* __restrict__ q, const float* __restrict__ k,
              const float* __restrict__ v, float* __restrict__ o) {
    extern __shared__ uint32_t smu[];
    uint32_t* sq = smu;              // 128 x 68 = 8704
    uint32_t* sk = smu + 8704;       // 64 x 68  = 4352
    uint32_t* sv = smu + 13056;      // 64 x 68  = 4352
    uint32_t* sp = smu + 17408;      // 128 x 36 = 4608
    const uint32_t sqb = smem_u32(sq);
    const uint32_t skb = smem_u32(sk);
    const uint32_t svb = smem_u32(sv);
    const uint32_t spb = smem_u32(sp);

    const int tid  = threadIdx.x;
    const int lane = tid & 31, w = tid >> 5;
    const int g = lane >> 2, c = lane & 3;
    const int qt = blockIdx.x, h = blockIdx.y, b = blockIdx.z;
    const int kv = h >> 2;
    const size_t rowbase = (size_t)b * SEQ;
    const int qrow0 = qt * 128;
    const int r0g = w * 16 + g;

    // ldmatrix lane addressing
    const int lmrow  = (lane & 7) + ((lane >> 3) & 1) * 8;   // A-side (Q, P)
    const int lmcol  = (lane >> 4) * 4;
    const int krow   = (lane & 7) + (lane >> 4) * 8;         // K B-side (2 nf blocks)
    const int kcolw  = ((lane >> 3) & 1) * 4;
    const int vrow   = (lane & 7) + ((lane >> 3) & 1) * 8;   // V trans blocks
    const int vcolw  = (lane >> 4) * 4;

    // load Q tile [128 x 128] -> half2
    #pragma unroll
    for (int u = 0; u < 16; u++) {
        int f = tid + 256 * u;
        int r = f >> 5, c4 = f & 31;
        float4 qa = *(const float4*)(q + (rowbase + qrow0 + r) * (NH * HD) + h * HD + c4 * 4);
        uint32_t* p = sq + r * 68 + c4 * 2;
        p[0] = pk(qa.x, qa.y); p[1] = pk(qa.z, qa.w);
    }

    float out[16][4] = {};
    float m0 = -1e30f, m1 = -1e30f, l0 = 0.f, l1 = 0.f;
    const float SCALE = 0.08838834764831845f;   // 1/sqrt(128)

    const int ktmax = 2 * qt + 1;
    for (int kt = 0; kt <= ktmax; kt++) {
        __syncthreads();   // previous tile's PV reads complete
        #pragma unroll
        for (int u = 0; u < 8; u++) {
            int f = tid + 256 * u;
            int r = f >> 5, c4 = f & 31;
            size_t src = (rowbase + kt * 64 + r) * (NKV * HD) + kv * HD + c4 * 4;
            float4 ka = *(const float4*)(k + src);
            float4 va = *(const float4*)(v + src);
            uint32_t* pkp = sk + r * 68 + c4 * 2;
            pkp[0] = pk(ka.x, ka.y); pkp[1] = pk(ka.z, ka.w);
            uint32_t* pvp = sv + r * 68 + c4 * 2;
            pvp[0] = pk(va.x, va.y); pvp[1] = pk(va.z, va.w);
        }
        __syncthreads();

        // S = Q K^T : warp computes 16 x 64 (8 ksteps of 16 along hd)
        float s[8][4] = {};
        #pragma unroll
        for (int ks = 0; ks < 8; ks++) {
            uint32_t a[4];
            LDSM4(a[0], a[1], a[2], a[3],
                  sqb + (uint32_t)(((w * 16 + lmrow) * 68 + ks * 8 + lmcol) * 4));
            #pragma unroll
            for (int nfp = 0; nfp < 4; nfp++) {
                uint32_t b0, b1, b2, b3;
                LDSM4(b0, b1, b2, b3,
                      skb + (uint32_t)(((nfp * 16 + krow) * 68 + ks * 8 + kcolw) * 4));
                uint32_t bA[2] = {b0, b1}, bB[2] = {b2, b3};
                mma16(s[2 * nfp],     a, bA);
                mma16(s[2 * nfp + 1], a, bB);
            }
        }

        // scale + causal mask
        const bool needmask = (kt >= 2 * qt);
        const int grow0 = qrow0 + r0g, grow1 = grow0 + 8;
        #pragma unroll
        for (int nf = 0; nf < 8; nf++) {
            int col = kt * 64 + nf * 8 + 2 * c;
            s[nf][0] = (needmask && col     > grow0) ? -1e30f : s[nf][0] * SCALE;
            s[nf][1] = (needmask && col + 1 > grow0) ? -1e30f : s[nf][1] * SCALE;
            s[nf][2] = (needmask && col     > grow1) ? -1e30f : s[nf][2] * SCALE;
            s[nf][3] = (needmask && col + 1 > grow1) ? -1e30f : s[nf][3] * SCALE;
        }

        // online softmax (fp32, 4-lane row groups)
        float rm0 = -1e30f, rm1 = -1e30f;
        #pragma unroll
        for (int nf = 0; nf < 8; nf++) {
            rm0 = fmaxf(rm0, fmaxf(s[nf][0], s[nf][1]));
            rm1 = fmaxf(rm1, fmaxf(s[nf][2], s[nf][3]));
        }
        #pragma unroll
        for (int off = 1; off < 4; off <<= 1) {
            rm0 = fmaxf(rm0, __shfl_xor_sync(0xffffffffu, rm0, off));
            rm1 = fmaxf(rm1, __shfl_xor_sync(0xffffffffu, rm1, off));
        }
        float mn0 = fmaxf(m0, rm0), mn1 = fmaxf(m1, rm1);
        float co0 = __expf(m0 - mn0), co1 = __expf(m1 - mn1);
        m0 = mn0; m1 = mn1;

        float rs0 = 0.f, rs1 = 0.f;
        #pragma unroll
        for (int nf = 0; nf < 8; nf++) {
            float p00 = __expf(s[nf][0] - mn0);
            float p01 = __expf(s[nf][1] - mn0);
            float p10 = __expf(s[nf][2] - mn1);
            float p11 = __expf(s[nf][3] - mn1);
            rs0 += p00 + p01;
            rs1 += p10 + p11;
            sp[r0g * 36 + nf * 4 + c]       = pk(p00, p01);
            sp[(r0g + 8) * 36 + nf * 4 + c] = pk(p10, p11);
        }
        #pragma unroll
        for (int off = 1; off < 4; off <<= 1) {
            rs0 += __shfl_xor_sync(0xffffffffu, rs0, off);
            rs1 += __shfl_xor_sync(0xffffffffu, rs1, off);
        }
        l0 = l0 * co0 + rs0;
        l1 = l1 * co1 + rs1;
        #pragma unroll
        for (int nf = 0; nf < 16; nf++) {
            out[nf][0] *= co0; out[nf][1] *= co0;
            out[nf][2] *= co1; out[nf][3] *= co1;
        }
        __syncwarp();   // sp rows are warp-private

        // out += P @ V : 4 ksteps of 16 keys; B frags via ldmatrix.trans
        #pragma unroll
        for (int ks = 0; ks < 4; ks++) {
            uint32_t a[4];
            LDSM4(a[0], a[1], a[2], a[3],
                  spb + (uint32_t)(((w * 16 + lmrow) * 36 + ks * 8 + lmcol) * 4));
            const uint32_t rowaddr = svb + (uint32_t)(((ks * 16 + vrow) * 68 + vcolw) * 4);
            #pragma unroll
            for (int nf2 = 0; nf2 < 8; nf2++) {
                uint32_t d0, d1, d2, d3;
                asm volatile(
                    "ldmatrix.sync.aligned.m8n8.x4.trans.shared.b16 "
                    "{%0,%1,%2,%3}, [%4];"
                    : "=r"(d0), "=r"(d1), "=r"(d2), "=r"(d3)
                    : "r"(rowaddr + (uint32_t)(nf2 * 8 * 4)));
                uint32_t bA[2] = {d0, d1}, bB[2] = {d2, d3};
                mma16(out[2 * nf2],     a, bA);
                mma16(out[2 * nf2 + 1], a, bB);
            }
        }
        __syncwarp();   // lanes done reading sp before next tile overwrites
    }

    // epilogue
    const float i0 = 1.f / l0, i1 = 1.f / l1;
    const size_t gr0 = rowbase + qrow0 + r0g;
    #pragma unroll
    for (int nf = 0; nf < 16; nf++) {
        const int col = h * HD + nf * 8 + 2 * c;
        *(float2*)(o + gr0 * (NH * HD) + col)       = make_float2(out[nf][0] * i0, out[nf][1] * i0);
        *(float2*)(o + (gr0 + 8) * (NH * HD) + col) = make_float2(out[nf][2] * i1, out[nf][3] * i1);
    }
}

// ---------------- launch ----------------------------------------------------
extern "C" void kernel_launch(void* const* d_in, const int* in_sizes, int n_in,
                              void* d_out, int out_size) {
    const float* x  = (const float*)d_in[0];
    const float* fc = (const float*)d_in[1];
    const float* fs = (const float*)d_in[2];
    const float* wq = (const float*)d_in[3];
    const float* wk = (const float*)d_in[4];
    const float* wv = (const float*)d_in[5];
    const float* wo = (const float*)d_in[6];
    float* out = (float*)d_out;

    float *q, *k, *v, *o;
    cudaGetSymbolAddress((void**)&q, g_q);
    cudaGetSymbolAddress((void**)&k, g_k);
    cudaGetSymbolAddress((void**)&v, g_v);
    cudaGetSymbolAddress((void**)&o, g_o);
    cudaFuncSetAttribute(attn_f16, cudaFuncAttributeMaxDynamicSharedMemorySize,
                         ATT_SMEM_BYTES);

    // projections (fp16 tensor cores)
    gemm_f16<<<dim3((NH  * HD) / 128, MROWS / 128), 256>>>(x, wq, q, NH  * HD, DMODEL);
    gemm_f16<<<dim3((NKV * HD) / 128, MROWS / 128), 256>>>(x, wk, k, NKV * HD, DMODEL);
    gemm_f16<<<dim3((NKV * HD) / 128, MROWS / 128), 256>>>(x, wv, v, NKV * HD, DMODEL);

    // rope
    {
        int tot = MROWS * NH * (HD / 2);
        rope_kernel<<<(tot + 255) / 256, 256>>>(q, fc, fs, NH, tot);
    }
    {
        int tot = MROWS * NKV * (HD / 2);
        rope_kernel<<<(tot + 255) / 256, 256>>>(k, fc, fs, NKV, tot);
    }

    // attention (fp16 mma flash attention)
    attn_f16<<<dim3(SEQ / 128, NH, BATCH), 256, ATT_SMEM_BYTES>>>(q, k, v, o);

    // output projection
    gemm_f16<<<dim3(DMODEL / 128, MROWS / 128), 256>>>(o, wo, out, DMODEL, DMODEL);
}

// round 11
// speedup vs baseline: 8.3531x; 1.4190x over previous
#include <cuda_runtime.h>
#include <cuda_fp16.h>
#include <cstdint>

#define BATCH 4
#define SEQ 2048
#define DMODEL 2048
#define NH 16
#define NKV 4
#define HD 128
#define MROWS (BATCH * SEQ)   // 8192

// ---------------- scratch (device globals: allocation-free) ----------------
__device__ __half g_xh[(size_t)MROWS * DMODEL];
__device__ __half g_wqh[(size_t)DMODEL * NH * HD];
__device__ __half g_wkh[(size_t)DMODEL * NKV * HD];
__device__ __half g_wvh[(size_t)DMODEL * NKV * HD];
__device__ __half g_woh[(size_t)NH * HD * DMODEL];
__device__ __half g_qh[(size_t)MROWS * NH * HD];
__device__ __half g_kh[(size_t)MROWS * NKV * HD];
__device__ __half g_vh[(size_t)MROWS * NKV * HD];
__device__ __half g_oh[(size_t)MROWS * NH * HD];

// ---------------- helpers ---------------------------------------------------
__device__ __forceinline__ uint32_t smem_u32(const void* p) {
    uint32_t a;
    asm("{ .reg .u64 t; cvta.to.shared.u64 t, %1; cvt.u32.u64 %0, t; }"
        : "=r"(a) : "l"(p));
    return a;
}

__device__ __forceinline__ void mma16(float c[4], const uint32_t a[4], const uint32_t b[2]) {
    asm volatile(
        "mma.sync.aligned.m16n8k16.row.col.f32.f16.f16.f32 "
        "{%0,%1,%2,%3}, {%4,%5,%6,%7}, {%8,%9}, {%0,%1,%2,%3};"
        : "+f"(c[0]), "+f"(c[1]), "+f"(c[2]), "+f"(c[3])
        : "r"(a[0]), "r"(a[1]), "r"(a[2]), "r"(a[3]), "r"(b[0]), "r"(b[1]));
}

#define LDSM4(r0, r1, r2, r3, addr)                                              \
    asm volatile("ldmatrix.sync.aligned.m8n8.x4.shared.b16 {%0,%1,%2,%3}, [%4];" \
        : "=r"(r0), "=r"(r1), "=r"(r2), "=r"(r3) : "r"(addr))
#define LDSM4T(r0, r1, r2, r3, addr)                                             \
    asm volatile("ldmatrix.sync.aligned.m8n8.x4.trans.shared.b16 {%0,%1,%2,%3}, [%4];" \
        : "=r"(r0), "=r"(r1), "=r"(r2), "=r"(r3) : "r"(addr))
#define CPA16(sa, gp) \
    asm volatile("cp.async.cg.shared.global [%0], [%1], 16;" :: "r"(sa), "l"(gp))
#define CPA_COMMIT() asm volatile("cp.async.commit_group;" ::: "memory")
#define CPA_WAIT(n)  asm volatile("cp.async.wait_group %0;" :: "n"(n) : "memory")

// ---------------- fp32 -> fp16 convert --------------------------------------
__global__ void f2h(const float* __restrict__ src, __half* __restrict__ dst, int n4) {
    int i = blockIdx.x * blockDim.x + threadIdx.x;
    if (i >= n4) return;
    float4 v = ((const float4*)src)[i];
    ((__half2*)dst)[2 * i]     = __floats2half2_rn(v.x, v.y);
    ((__half2*)dst)[2 * i + 1] = __floats2half2_rn(v.z, v.w);
}

// ---------------- half GEMM: C[M,N] = A[M,K] @ B[K,N] ----------------------
// A,B half row-major. CTA tile 128x128, k-tile 64, 3-stage cp.async pipeline.
// smem/stage: A 128 rows x 36 words (18432B) | B 64 rows x 68 words (17408B).
#define GEMM_SMEM_BYTES 107520
template <bool OUTH>
__global__ __launch_bounds__(256, 2)
void gemm_h(const __half* __restrict__ A, const __half* __restrict__ B,
            void* __restrict__ Cv, int N, int K) {
    extern __shared__ char sm[];
    const uint32_t sb = smem_u32(sm);
    const int tid  = threadIdx.x;
    const int lane = tid & 31, w = tid >> 5;
    const int g = lane >> 2, c = lane & 3;
    const int wm = (w & 3) * 32, wn = (w >> 2) * 64;
    const int m0 = blockIdx.y * 128, n0 = blockIdx.x * 128;

    const int lmrow = (lane & 7) + ((lane >> 3) & 1) * 8;   // A non-trans
    const int lmcol = (lane >> 4) * 4;
    const int vrow  = (lane & 7) + ((lane >> 3) & 1) * 8;   // B trans
    const int vcolw = (lane >> 4) * 4;

    const int ar = tid >> 3, ach = tid & 7;     // A: 128r x 8ch, 4 passes
    const int br16 = tid >> 4, bch = tid & 15;  // B: 64r x 16ch, 4 passes

    const int nt = K >> 6;
    float acc[2][8][4] = {};

    auto issue = [&](int t, int s) {
        const int k0 = t << 6;
        const uint32_t st = sb + (uint32_t)s * 35840u;
        #pragma unroll
        for (int p = 0; p < 4; p++) {
            int r = ar + 32 * p;
            CPA16(st + (uint32_t)(r * 144 + ach * 16),
                  A + (size_t)(m0 + r) * K + k0 + ach * 8);
        }
        #pragma unroll
        for (int p = 0; p < 4; p++) {
            int r = br16 + 16 * p;
            CPA16(st + 18432u + (uint32_t)(r * 272 + bch * 16),
                  B + (size_t)(k0 + r) * N + n0 + bch * 8);
        }
        CPA_COMMIT();
    };

    issue(0, 0);
    if (nt > 1) issue(1, 1);

    for (int i = 0; i < nt; i++) {
        const int s = i % 3;
        if (i == nt - 1) { CPA_WAIT(0); } else { CPA_WAIT(1); }
        __syncthreads();

        const uint32_t sA = sb + (uint32_t)s * 35840u;
        const uint32_t sB = sA + 18432u;
        #pragma unroll
        for (int ks = 0; ks < 4; ks++) {
            uint32_t a[2][4];
            #pragma unroll
            for (int mf = 0; mf < 2; mf++)
                LDSM4(a[mf][0], a[mf][1], a[mf][2], a[mf][3],
                      sA + (uint32_t)(((wm + mf * 16 + lmrow) * 36 + ks * 8 + lmcol) * 4));
            const uint32_t baddr = sB +
                (uint32_t)(((ks * 16 + vrow) * 68 + (wn >> 1) + vcolw) * 4);
            #pragma unroll
            for (int nf2 = 0; nf2 < 4; nf2++) {
                uint32_t d0, d1, d2, d3;
                LDSM4T(d0, d1, d2, d3, baddr + (uint32_t)(nf2 * 32));
                uint32_t bA[2] = {d0, d1}, bB[2] = {d2, d3};
                #pragma unroll
                for (int mf = 0; mf < 2; mf++) {
                    mma16(acc[mf][2 * nf2],     a[mf], bA);
                    mma16(acc[mf][2 * nf2 + 1], a[mf], bB);
                }
            }
        }
        if (i + 2 < nt) issue(i + 2, (i + 2) % 3);
    }

    #pragma unroll
    for (int mf = 0; mf < 2; mf++) {
        const size_t r0 = (size_t)(m0 + wm + mf * 16 + g);
        #pragma unroll
        for (int nf = 0; nf < 8; nf++) {
            const int col = n0 + wn + nf * 8 + 2 * c;
            if (OUTH) {
                __half* C = (__half*)Cv;
                *(__half2*)(C + r0 * N + col) =
                    __floats2half2_rn(acc[mf][nf][0], acc[mf][nf][1]);
                *(__half2*)(C + (r0 + 8) * N + col) =
                    __floats2half2_rn(acc[mf][nf][2], acc[mf][nf][3]);
            } else {
                float* C = (float*)Cv;
                *(float2*)(C + r0 * N + col)       = make_float2(acc[mf][nf][0], acc[mf][nf][1]);
                *(float2*)(C + (r0 + 8) * N + col) = make_float2(acc[mf][nf][2], acc[mf][nf][3]);
            }
        }
    }
}

// ---------------- RoPE on half (interleaved pairs) --------------------------
__global__ void rope_h(__half* __restrict__ buf, const float* __restrict__ fc,
                       const float* __restrict__ fs, int heads, int total) {
    int idx = blockIdx.x * blockDim.x + threadIdx.x;
    if (idx >= total) return;
    int i   = idx & (HD / 2 - 1);
    int rh  = idx >> 6;
    int h   = rh % heads;
    int row = rh / heads;
    int s   = row & (SEQ - 1);
    float cv = fc[s * (HD / 2) + i];
    float sv = fs[s * (HD / 2) + i];
    __half2* p = (__half2*)(buf + (size_t)row * heads * HD + h * HD) + i;
    float2 xv = __half22float2(*p);
    *p = __floats2half2_rn(xv.x * cv - xv.y * sv, xv.x * sv + xv.y * cv);
}

// ---------------- flash attention, fp16 mma, causal, GQA -------------------
// CTA: 128 Q rows, 8 warps x 16 rows; K/V tile 64. Grid (SEQ/128, NH, B).
// smem words: sq 128x68 | sk 64x68 | sv 64x68 | sp 128x36
#define ATT_SMEM_BYTES 88064
__global__ __launch_bounds__(256)
void attn_f16(const __half* __restrict__ q, const __half* __restrict__ k,
              const __half* __restrict__ v, __half* __restrict__ o) {
    extern __shared__ uint32_t smu[];
    uint32_t* sp = smu + 17408;
    const uint32_t sqb = smem_u32(smu);
    const uint32_t skb = sqb + 8704 * 4;
    const uint32_t svb = sqb + 13056 * 4;
    const uint32_t spb = sqb + 17408 * 4;

    const int tid  = threadIdx.x;
    const int lane = tid & 31, w = tid >> 5;
    const int g = lane >> 2, c = lane & 3;
    const int qt = blockIdx.x, h = blockIdx.y, b = blockIdx.z;
    const int kv = h >> 2;
    const size_t rowbase = (size_t)b * SEQ;
    const int qrow0 = qt * 128;
    const int r0g = w * 16 + g;

    const int lmrow = (lane & 7) + ((lane >> 3) & 1) * 8;   // A-side (Q, P)
    const int lmcol = (lane >> 4) * 4;
    const int krow  = (lane & 7) + (lane >> 4) * 8;         // K B-side
    const int kcolw = ((lane >> 3) & 1) * 4;
    const int vrow  = (lane & 7) + ((lane >> 3) & 1) * 8;   // V trans
    const int vcolw = (lane >> 4) * 4;

    const int sr16 = tid >> 4, sch = tid & 15;  // staging: 16 chunks/row

    // Q tile [128 x 128 halfs] via cp.async: 128 rows x 16 chunks, 8 passes
    #pragma unroll
    for (int p = 0; p < 8; p++) {
        int r = sr16 + 16 * p;
        CPA16(sqb + (uint32_t)(r * 272 + sch * 16),
              q + (rowbase + qrow0 + r) * (NH * HD) + h * HD + sch * 8);
    }
    CPA_COMMIT();

    float out[16][4] = {};
    float m0 = -1e30f, m1 = -1e30f, l0 = 0.f, l1 = 0.f;
    const float SCALE = 0.08838834764831845f;   // 1/sqrt(128)

    const int ktmax = 2 * qt + 1;
    for (int kt = 0; kt <= ktmax; kt++) {
        __syncthreads();   // previous tile's reads of sk/sv/sp complete
        #pragma unroll
        for (int p = 0; p < 4; p++) {
            int r = sr16 + 16 * p;
            size_t src = (rowbase + kt * 64 + r) * (NKV * HD) + kv * HD + sch * 8;
            CPA16(skb + (uint32_t)(r * 272 + sch * 16), k + src);
            CPA16(svb + (uint32_t)(r * 272 + sch * 16), v + src);
        }
        CPA_COMMIT();
        CPA_WAIT(0);
        __syncthreads();

        // S = Q K^T
        float s[8][4] = {};
        #pragma unroll
        for (int ks = 0; ks < 8; ks++) {
            uint32_t a[4];
            LDSM4(a[0], a[1], a[2], a[3],
                  sqb + (uint32_t)(((w * 16 + lmrow) * 68 + ks * 8 + lmcol) * 4));
            #pragma unroll
            for (int nfp = 0; nfp < 4; nfp++) {
                uint32_t b0, b1, b2, b3;
                LDSM4(b0, b1, b2, b3,
                      skb + (uint32_t)(((nfp * 16 + krow) * 68 + ks * 8 + kcolw) * 4));
                uint32_t bA[2] = {b0, b1}, bB[2] = {b2, b3};
                mma16(s[2 * nfp],     a, bA);
                mma16(s[2 * nfp + 1], a, bB);
            }
        }

        // scale + causal mask
        const bool needmask = (kt >= 2 * qt);
        const int grow0 = qrow0 + r0g, grow1 = grow0 + 8;
        #pragma unroll
        for (int nf = 0; nf < 8; nf++) {
            int col = kt * 64 + nf * 8 + 2 * c;
            s[nf][0] = (needmask && col     > grow0) ? -1e30f : s[nf][0] * SCALE;
            s[nf][1] = (needmask && col + 1 > grow0) ? -1e30f : s[nf][1] * SCALE;
            s[nf][2] = (needmask && col     > grow1) ? -1e30f : s[nf][2] * SCALE;
            s[nf][3] = (needmask && col + 1 > grow1) ? -1e30f : s[nf][3] * SCALE;
        }

        // online softmax (fp32, 4-lane row groups)
        float rm0 = -1e30f, rm1 = -1e30f;
        #pragma unroll
        for (int nf = 0; nf < 8; nf++) {
            rm0 = fmaxf(rm0, fmaxf(s[nf][0], s[nf][1]));
            rm1 = fmaxf(rm1, fmaxf(s[nf][2], s[nf][3]));
        }
        #pragma unroll
        for (int off = 1; off < 4; off <<= 1) {
            rm0 = fmaxf(rm0, __shfl_xor_sync(0xffffffffu, rm0, off));
            rm1 = fmaxf(rm1, __shfl_xor_sync(0xffffffffu, rm1, off));
        }
        float mn0 = fmaxf(m0, rm0), mn1 = fmaxf(m1, rm1);
        float co0 = __expf(m0 - mn0), co1 = __expf(m1 - mn1);
        m0 = mn0; m1 = mn1;

        float rs0 = 0.f, rs1 = 0.f;
        #pragma unroll
        for (int nf = 0; nf < 8; nf++) {
            float p00 = __expf(s[nf][0] - mn0);
            float p01 = __expf(s[nf][1] - mn0);
            float p10 = __expf(s[nf][2] - mn1);
            float p11 = __expf(s[nf][3] - mn1);
            rs0 += p00 + p01;
            rs1 += p10 + p11;
            __half2 h0 = __floats2half2_rn(p00, p01);
            __half2 h1 = __floats2half2_rn(p10, p11);
            sp[r0g * 36 + nf * 4 + c]       = *(uint32_t*)&h0;
            sp[(r0g + 8) * 36 + nf * 4 + c] = *(uint32_t*)&h1;
        }
        #pragma unroll
        for (int off = 1; off < 4; off <<= 1) {
            rs0 += __shfl_xor_sync(0xffffffffu, rs0, off);
            rs1 += __shfl_xor_sync(0xffffffffu, rs1, off);
        }
        l0 = l0 * co0 + rs0;
        l1 = l1 * co1 + rs1;
        #pragma unroll
        for (int nf = 0; nf < 16; nf++) {
            out[nf][0] *= co0; out[nf][1] *= co0;
            out[nf][2] *= co1; out[nf][3] *= co1;
        }
        __syncwarp();   // sp rows warp-private

        // out += P @ V
        #pragma unroll
        for (int ks = 0; ks < 4; ks++) {
            uint32_t a[4];
            LDSM4(a[0], a[1], a[2], a[3],
                  spb + (uint32_t)(((w * 16 + lmrow) * 36 + ks * 8 + lmcol) * 4));
            const uint32_t rowaddr = svb + (uint32_t)(((ks * 16 + vrow) * 68 + vcolw) * 4);
            #pragma unroll
            for (int nf2 = 0; nf2 < 8; nf2++) {
                uint32_t d0, d1, d2, d3;
                LDSM4T(d0, d1, d2, d3, rowaddr + (uint32_t)(nf2 * 32));
                uint32_t bA[2] = {d0, d1}, bB[2] = {d2, d3};
                mma16(out[2 * nf2],     a, bA);
                mma16(out[2 * nf2 + 1], a, bB);
            }
        }
        __syncwarp();
    }

    // epilogue (half output)
    const float i0 = 1.f / l0, i1 = 1.f / l1;
    const size_t gr0 = rowbase + qrow0 + r0g;
    #pragma unroll
    for (int nf = 0; nf < 16; nf++) {
        const int col = h * HD + nf * 8 + 2 * c;
        *(__half2*)(o + gr0 * (NH * HD) + col) =
            __floats2half2_rn(out[nf][0] * i0, out[nf][1] * i0);
        *(__half2*)(o + (gr0 + 8) * (NH * HD) + col) =
            __floats2half2_rn(out[nf][2] * i1, out[nf][3] * i1);
    }
}

// ---------------- launch ----------------------------------------------------
extern "C" void kernel_launch(void* const* d_in, const int* in_sizes, int n_in,
                              void* d_out, int out_size) {
    const float* x  = (const float*)d_in[0];
    const float* fc = (const float*)d_in[1];
    const float* fs = (const float*)d_in[2];
    const float* wq = (const float*)d_in[3];
    const float* wk = (const float*)d_in[4];
    const float* wv = (const float*)d_in[5];
    const float* wo = (const float*)d_in[6];
    float* out = (float*)d_out;

    __half *xh, *wqh, *wkh, *wvh, *woh, *qh, *kh, *vh, *oh;
    cudaGetSymbolAddress((void**)&xh,  g_xh);
    cudaGetSymbolAddress((void**)&wqh, g_wqh);
    cudaGetSymbolAddress((void**)&wkh, g_wkh);
    cudaGetSymbolAddress((void**)&wvh, g_wvh);
    cudaGetSymbolAddress((void**)&woh, g_woh);
    cudaGetSymbolAddress((void**)&qh,  g_qh);
    cudaGetSymbolAddress((void**)&kh,  g_kh);
    cudaGetSymbolAddress((void**)&vh,  g_vh);
    cudaGetSymbolAddress((void**)&oh,  g_oh);

    cudaFuncSetAttribute(attn_f16, cudaFuncAttributeMaxDynamicSharedMemorySize,
                         ATT_SMEM_BYTES);
    cudaFuncSetAttribute(gemm_h<true>, cudaFuncAttributeMaxDynamicSharedMemorySize,
                         GEMM_SMEM_BYTES);
    cudaFuncSetAttribute(gemm_h<false>, cudaFuncAttributeMaxDynamicSharedMemorySize,
                         GEMM_SMEM_BYTES);

    // convert inputs to half
    {
        int n4;
        n4 = MROWS * DMODEL / 4;        f2h<<<(n4 + 255) / 256, 256>>>(x,  xh,  n4);
        n4 = DMODEL * NH * HD / 4;      f2h<<<(n4 + 255) / 256, 256>>>(wq, wqh, n4);
        n4 = DMODEL * NKV * HD / 4;     f2h<<<(n4 + 255) / 256, 256>>>(wk, wkh, n4);
        n4 = DMODEL * NKV * HD / 4;     f2h<<<(n4 + 255) / 256, 256>>>(wv, wvh, n4);
        n4 = NH * HD * DMODEL / 4;      f2h<<<(n4 + 255) / 256, 256>>>(wo, woh, n4);
    }

    // projections (half in, half out)
    gemm_h<true><<<dim3((NH  * HD) / 128, MROWS / 128), 256, GEMM_SMEM_BYTES>>>(
        xh, wqh, qh, NH * HD, DMODEL);
    gemm_h<true><<<dim3((NKV * HD) / 128, MROWS / 128), 256, GEMM_SMEM_BYTES>>>(
        xh, wkh, kh, NKV * HD, DMODEL);
    gemm_h<true><<<dim3((NKV * HD) / 128, MROWS / 128), 256, GEMM_SMEM_BYTES>>>(
        xh, wvh, vh, NKV * HD, DMODEL);

    // rope (on half)
    {
        int tot = MROWS * NH * (HD / 2);
        rope_h<<<(tot + 255) / 256, 256>>>(qh, fc, fs, NH, tot);
    }
    {
        int tot = MROWS * NKV * (HD / 2);
        rope_h<<<(tot + 255) / 256, 256>>>(kh, fc, fs, NKV, tot);
    }

    // attention (half in, half out)
    attn_f16<<<dim3(SEQ / 128, NH, BATCH), 256, ATT_SMEM_BYTES>>>(qh, kh, vh, oh);

    // output projection (half in, float out)
    gemm_h<false><<<dim3(DMODEL / 128, MROWS / 128), 256, GEMM_SMEM_BYTES>>>(
        oh, woh, out, DMODEL, DMODEL);
}